// round 6
// baseline (speedup 1.0000x reference)
#include <cuda_runtime.h>
#include <cuda_bf16.h>
#include <cstdint>

#define EPS_F      1e-8f
#define EPS4_F     4e-8f                 // 4*EPS  (clip on raw squares)
#define EPS16_F    1.6e-7f               // 16*EPS (clip on z product)
#define EPS64_F    6.4e-7f               // 64*EPS (clip on raw det)
#define TAU4_INV   13.333333333333334f   // 4/0.3 (cube-root 1/64 folded in)
#define LOG2E_F    1.4426950408889634f

static constexpr int NT  = 256;
static constexpr int NB1 = 1024;
static constexpr int BPT = 4;            // boxes per thread (28 floats = 7 float4 per tensor)

__device__ float2       g_partials[NB1];
__device__ unsigned int g_done_count;

__device__ __forceinline__ float warp_sum(float v) {
    #pragma unroll
    for (int off = 16; off > 0; off >>= 1)
        v += __shfl_xor_sync(0xFFFFFFFFu, v, off);
    return v;
}
__device__ __forceinline__ float fsqrt_ap(float x) {
    float r; asm("sqrt.approx.f32 %0, %1;" : "=f"(r) : "f"(x)); return r;
}
__device__ __forceinline__ float ex2_ap(float x) {
    float r; asm("ex2.approx.f32 %0, %1;" : "=f"(r) : "f"(x)); return r;
}
__device__ __forceinline__ float lg2_ap(float x) {
    float r; asm("lg2.approx.f32 %0, %1;" : "=f"(r) : "f"(x)); return r;
}

// per-box loss; covariance factor 0.25 folded out algebraically
__device__ __forceinline__ void box_loss(
    float p0, float p1, float p2, float p3, float p4v, float p5, float p6,
    float g0, float g1, float g2, float g3, float g4v, float g5, float g6,
    float& lsum, float& msum)
{
    float dx = p0 - g0, dy = p1 - g1, dz = p2 - g2;
    float mu = fmaf(dx, dx, fmaf(dy, dy, dz * dz));

    float tp = p3 * p3, up = p4v * p4v, vp = p5 * p5;
    float tt = g3 * g3, ut = g4v * g4v, vt = g5 * g5;

    float mtp = fmaxf(tp, EPS4_F);
    float mup = fmaxf(up, EPS4_F);
    float mvp = fmaxf(vp, EPS4_F);

    float cd = __cosf(p6 - g6);
    float cc = cd * cd;
    float ss = 1.0f - cc;
    float t1 = mtp * tt, t2 = mup * ut;
    float t3 = mtp * ut, t4 = mup * tt;
    float trM = fmaf(cc, t1 + t2, ss * (t3 + t4));
    float trS = fsqrt_ap(fmaf(2.0f, fsqrt_ap(t1 * t2), trM));   // sqrt(l1)+sqrt(l2)

    float sz = fsqrt_ap(fmaxf(mvp * vt, EPS16_F));

    float traces = (tp + up + vp) + (tt + ut + vt);
    float w2 = fmaf(0.25f, traces - 2.0f * (trS + sz), mu);

    float detr = fmaxf(tt * ut * vt, EPS64_F);
    float invd = ex2_ap(lg2_ap(detr) * (-1.0f / 3.0f)) * TAU4_INV;

    float loss = 1.0f - ex2_ap(-w2 * invd * LOG2E_F);
    if (g0 != 0.0f) { lsum += loss; msum += 1.0f; }
}

__global__ __launch_bounds__(NT) void gwd_fused(
    const float* __restrict__ pred,
    const float* __restrict__ gt,
    float* __restrict__ out,
    int total)
{
    const int nquads = total >> 2;           // groups of 4 boxes
    const int rem    = total & 3;

    float lsum = 0.0f;
    float msum = 0.0f;

    for (int q = blockIdx.x * NT + threadIdx.x; q < nquads; q += gridDim.x * NT) {
        // 4 boxes = 28 floats = 7 float4 per tensor, 16B-aligned (28*4=112 | 16)
        const float4* __restrict__ p4 = (const float4*)(pred + 28ll * q);
        const float4* __restrict__ g4 = (const float4*)(gt   + 28ll * q);

        // all 14 LDG.128 issued up front -> max MLP, perfectly coalesced
        float4 P0 = p4[0], P1 = p4[1], P2 = p4[2], P3 = p4[3],
               P4 = p4[4], P5 = p4[5], P6 = p4[6];
        float4 G0 = g4[0], G1 = g4[1], G2 = g4[2], G3 = g4[3],
               G4 = g4[4], G5 = g4[5], G6 = g4[6];

        // unpack (register renaming only)
        // box0: p[0..6]  = P0.xyzw P1.xyz
        box_loss(P0.x, P0.y, P0.z, P0.w, P1.x, P1.y, P1.z,
                 G0.x, G0.y, G0.z, G0.w, G1.x, G1.y, G1.z, lsum, msum);
        // box1: p[7..13] = P1.w P2.xyzw P3.xy
        box_loss(P1.w, P2.x, P2.y, P2.z, P2.w, P3.x, P3.y,
                 G1.w, G2.x, G2.y, G2.z, G2.w, G3.x, G3.y, lsum, msum);
        // box2: p[14..20] = P3.zw P4.xyzw P5.x
        box_loss(P3.z, P3.w, P4.x, P4.y, P4.z, P4.w, P5.x,
                 G3.z, G3.w, G4.x, G4.y, G4.z, G4.w, G5.x, lsum, msum);
        // box3: p[21..27] = P5.yzw P6.xyzw
        box_loss(P5.y, P5.z, P5.w, P6.x, P6.y, P6.z, P6.w,
                 G5.y, G5.z, G5.w, G6.x, G6.y, G6.z, G6.w, lsum, msum);
    }

    // ragged tail (0 for this shape)
    if (rem && blockIdx.x == 0 && threadIdx.x < rem) {
        const int b = nquads * 4 + threadIdx.x;
        const float* p = pred + 7ll * b;
        const float* g = gt   + 7ll * b;
        box_loss(p[0], p[1], p[2], p[3], p[4], p[5], p[6],
                 g[0], g[1], g[2], g[3], g[4], g[5], g[6], lsum, msum);
    }

    // block reduction
    lsum = warp_sum(lsum);
    msum = warp_sum(msum);

    __shared__ float sl[NT / 32];
    __shared__ float sm[NT / 32];
    int lane = threadIdx.x & 31;
    int wid  = threadIdx.x >> 5;
    if (lane == 0) { sl[wid] = lsum; sm[wid] = msum; }
    __syncthreads();

    __shared__ bool is_last;
    if (threadIdx.x == 0) {
        float vl = 0.0f, vm = 0.0f;
        #pragma unroll
        for (int w = 0; w < NT / 32; w++) { vl += sl[w]; vm += sm[w]; }
        g_partials[blockIdx.x] = make_float2(vl, vm);
        __threadfence();
        unsigned int ticket = atomicAdd(&g_done_count, 1u);
        is_last = (ticket == (unsigned)(gridDim.x - 1));
    }
    __syncthreads();

    // last block finalizes (deterministic order)
    if (is_last) {
        double l = 0.0, m = 0.0;
        for (int i = threadIdx.x; i < NB1; i += NT) {
            float2 v = g_partials[i];
            l += (double)v.x;
            m += (double)v.y;
        }
        #pragma unroll
        for (int off = 16; off > 0; off >>= 1) {
            l += __shfl_xor_sync(0xFFFFFFFFu, l, off);
            m += __shfl_xor_sync(0xFFFFFFFFu, m, off);
        }
        __shared__ double dl[NT / 32];
        __shared__ double dm[NT / 32];
        if (lane == 0) { dl[wid] = l; dm[wid] = m; }
        __syncthreads();
        if (threadIdx.x == 0) {
            double vl = 0.0, vm = 0.0;
            #pragma unroll
            for (int w = 0; w < NT / 32; w++) { vl += dl[w]; vm += dm[w]; }
            out[0] = (float)(vl / (vm + (double)EPS_F));
            g_done_count = 0;   // reset for next graph replay
        }
    }
}

extern "C" void kernel_launch(void* const* d_in, const int* in_sizes, int n_in,
                              void* d_out, int out_size)
{
    const float* pred = (const float*)d_in[0];
    const float* gt   = (const float*)d_in[1];
    float* out = (float*)d_out;

    int total = in_sizes[0] / 7;

    gwd_fused<<<NB1, NT>>>(pred, gt, out, total);
}